// round 14
// baseline (speedup 1.0000x reference)
#include <cuda_runtime.h>
#include <cuda_fp16.h>
#include <cstdint>
#include <cstddef>

#define NODES 100000
#define EDGES 1600000

// ---------------------------------------------------------------------------
// Scratch (__device__ globals; no allocation allowed anywhere).
// ---------------------------------------------------------------------------
__device__ float g_p1[(size_t)NODES * 128];            // layer1: x@W1_r (fp32)
__device__ unsigned short g_t1[(size_t)NODES * 128];   // layer1: x@W1_l (fp16)
__device__ unsigned short g_hh[(size_t)NODES * 128];   // h (fp16, single plane)
__device__ float g_p2[(size_t)NODES * 64];             // layer2: h@W2_r (fp32)
__device__ unsigned short g_t2[(size_t)NODES * 64];    // layer2: h@W2_l (fp16)
__device__ int   g_count[NODES];
__device__ int   g_rowptr[NODES + 1];
__device__ int   g_cursor[NODES];
__device__ int   g_srcidx[EDGES];
// Pre-transposed fp16 weights: Bt[n][k], n = output col.
__device__ unsigned short g_bt1h[256 * 128];
__device__ unsigned short g_bt2h[128 * 128];

// ---------------------------------------------------------------------------
// CSR build: zero counts -> histogram -> scan -> fill
// ---------------------------------------------------------------------------
__global__ void zero_count_kernel() {
    int i = blockIdx.x * blockDim.x + threadIdx.x;
    if (i < NODES) g_count[i] = 0;
}

__global__ void hist_kernel(const int* __restrict__ edst, int E) {
    int i = blockIdx.x * blockDim.x + threadIdx.x;
    if (i < E) atomicAdd(&g_count[__ldg(edst + i)], 1);
}

__global__ void scan_kernel(int E) {
    __shared__ int sums[1024];
    const int tid = threadIdx.x;
    const int CH = (NODES + 1023) / 1024;
    const int beg = tid * CH;
    const int end = min(beg + CH, NODES);
    int s = 0;
    for (int i = beg; i < end; i++) s += g_count[i];
    sums[tid] = s;
    __syncthreads();
    for (int off = 1; off < 1024; off <<= 1) {
        int v = (tid >= off) ? sums[tid - off] : 0;
        __syncthreads();
        sums[tid] += v;
        __syncthreads();
    }
    int run = (tid == 0) ? 0 : sums[tid - 1];
    for (int i = beg; i < end; i++) {
        g_rowptr[i] = run;
        g_cursor[i] = run;
        run += g_count[i];
    }
    if (tid == 0) g_rowptr[NODES] = E;
}

__global__ void fill_kernel(const int* __restrict__ esrc,
                            const int* __restrict__ edst, int E) {
    int i = blockIdx.x * blockDim.x + threadIdx.x;
    if (i >= E) return;
    int d = __ldg(edst + i);
    int s = __ldg(esrc + i);
    int pos = atomicAdd(&g_cursor[d], 1);
    g_srcidx[pos] = s;
}

// ---------------------------------------------------------------------------
// Weight prep: transpose to [n][k], fp16.
// ---------------------------------------------------------------------------
__global__ void prep_weights(const float* __restrict__ W1r,
                             const float* __restrict__ W1l,
                             const float* __restrict__ W2r,
                             const float* __restrict__ W2l) {
    int b = blockIdx.x;
    int k = threadIdx.x;
    float v;
    unsigned short* dh;
    if (b < 256) {
        int n = b;
        const float* W = (n < 128) ? W1r : W1l;
        v = __ldg(W + (size_t)k * 128 + (n & 127));
        dh = g_bt1h + n * 128 + k;
    } else {
        int n = b - 256;
        const float* W = (n < 64) ? W2r : W2l;
        v = __ldg(W + (size_t)k * 64 + (n & 63));
        dh = g_bt2h + n * 128 + k;
    }
    *dh = __half_as_ushort(__float2half_rn(v));
}

// ---------------------------------------------------------------------------
// GEMM helpers (mma.sync.m16n8k16.f16 + ldmatrix).
// ---------------------------------------------------------------------------
#define LDKB 272   // smem bytes per 128-col fp16 row (136 * 2)

__device__ __forceinline__ uint32_t smem_u32(const void* p) {
    uint32_t a;
    asm("{ .reg .u64 t; cvta.to.shared.u64 t, %1; cvt.u32.u64 %0, t; }"
        : "=r"(a) : "l"(p));
    return a;
}

__device__ __forceinline__ void ldsm_x4(uint32_t r[4], uint32_t addr) {
    asm volatile("ldmatrix.sync.aligned.m8n8.x4.shared.b16 {%0,%1,%2,%3}, [%4];"
                 : "=r"(r[0]), "=r"(r[1]), "=r"(r[2]), "=r"(r[3]) : "r"(addr));
}

__device__ __forceinline__ void mma_f16(float c[4], const uint32_t a[4],
                                        const uint32_t b0, const uint32_t b1) {
    asm volatile(
        "mma.sync.aligned.m16n8k16.row.col.f32.f16.f16.f32 "
        "{%0,%1,%2,%3}, {%4,%5,%6,%7}, {%8,%9}, {%0,%1,%2,%3};"
        : "+f"(c[0]), "+f"(c[1]), "+f"(c[2]), "+f"(c[3])
        : "r"(a[0]), "r"(a[1]), "r"(a[2]), "r"(a[3]), "r"(b0), "r"(b1));
}

__device__ __forceinline__ uint32_t pack_half2(float a, float b) {
    __half2 h = __floats2half2_rn(a, b);
    return *reinterpret_cast<uint32_t*>(&h);
}

__device__ __forceinline__ void acc8_add(float acc[8], uint4 v) {
    float2 f0 = __half22float2(*reinterpret_cast<__half2*>(&v.x));
    float2 f1 = __half22float2(*reinterpret_cast<__half2*>(&v.y));
    float2 f2 = __half22float2(*reinterpret_cast<__half2*>(&v.z));
    float2 f3 = __half22float2(*reinterpret_cast<__half2*>(&v.w));
    acc[0] += f0.x; acc[1] += f0.y; acc[2] += f1.x; acc[3] += f1.y;
    acc[4] += f2.x; acc[5] += f2.y; acc[6] += f3.x; acc[7] += f3.y;
}

// ---------------------------------------------------------------------------
// gemm1 (merged-loop): per CTA, A[128x128 fp32 -> fp16 h/l] loaded ONCE;
// loop over two 128-col B halves reusing the A smem.
//   half 0 (Bt rows   0..127): 2 passes (ah+al) -> p1 fp32
//   half 1 (Bt rows 128..255): 1 pass  (ah)     -> t1 fp16
// SMEM = Ah + Al + Bh = 104448 -> 2 CTAs/SM.
// ---------------------------------------------------------------------------
#define SMEM1 (3 * 128 * LDKB)

__global__ void __launch_bounds__(256, 2) gemm1_tc(
    const float* __restrict__ A,
    const unsigned short* __restrict__ Bth,
    float* __restrict__ p1,
    unsigned short* __restrict__ t1,
    int Nrows) {
    extern __shared__ __align__(16) char smem[];
    constexpr int AH = 0;
    constexpr int AL = 128 * LDKB;
    constexpr int BH = 2 * 128 * LDKB;

    const int tid = threadIdx.x;
    const int row0 = blockIdx.x * 128;

    // ---- A tile: load fp32, split to fp16 hi/lo (once) ----
#pragma unroll
    for (int i = 0; i < 16; i++) {
        int l = tid + i * 256;
        int r = l >> 5;
        int k4 = (l & 31) * 4;
        float4 v = make_float4(0.f, 0.f, 0.f, 0.f);
        int gr = row0 + r;
        if (gr < Nrows)
            v = __ldg(reinterpret_cast<const float4*>(A + (size_t)gr * 128 + k4));
        __half h0 = __float2half_rn(v.x), h1 = __float2half_rn(v.y);
        __half h2 = __float2half_rn(v.z), h3 = __float2half_rn(v.w);
        uint32_t ph0 = (uint32_t)__half_as_ushort(h0) |
                       ((uint32_t)__half_as_ushort(h1) << 16);
        uint32_t ph1 = (uint32_t)__half_as_ushort(h2) |
                       ((uint32_t)__half_as_ushort(h3) << 16);
        __half q0 = __float2half_rn(v.x - __half2float(h0));
        __half q1 = __float2half_rn(v.y - __half2float(h1));
        __half q2 = __float2half_rn(v.z - __half2float(h2));
        __half q3 = __float2half_rn(v.w - __half2float(h3));
        uint32_t pl0 = (uint32_t)__half_as_ushort(q0) |
                       ((uint32_t)__half_as_ushort(q1) << 16);
        uint32_t pl1 = (uint32_t)__half_as_ushort(q2) |
                       ((uint32_t)__half_as_ushort(q3) << 16);
        int off = r * LDKB + k4 * 2;
        *reinterpret_cast<uint2*>(smem + AH + off) = make_uint2(ph0, ph1);
        *reinterpret_cast<uint2*>(smem + AL + off) = make_uint2(pl0, pl1);
    }

    const int wid = tid >> 5;
    const int lane = tid & 31;
    const int lane8 = lane & 7;
    const int lt = lane >> 3;
    const int gid = lane >> 2;
    const int tig = lane & 3;
    const int wm = (wid & 3) * 32;
    const int wn = (wid >> 2) * 64;

    const uint32_t sb = smem_u32(smem);
    const uint32_t aoff0 = sb + (uint32_t)((wm + (lt & 1) * 8 + lane8) * LDKB +
                                           (lt >> 1) * 16);
    const uint32_t boff0 = sb + BH +
                           (uint32_t)((wn + (lt >> 1) * 8 + lane8) * LDKB +
                                      (lt & 1) * 16);

#pragma unroll
    for (int half = 0; half < 2; half++) {
        if (half) __syncthreads();
#pragma unroll
        for (int i = 0; i < 8; i++) {
            int l = tid + i * 256;
            int n = l >> 4;
            int k8 = (l & 15) * 8;
            uint4 vh = __ldg(reinterpret_cast<const uint4*>(
                Bth + ((size_t)(half * 128 + n)) * 128 + k8));
            *reinterpret_cast<uint4*>(smem + BH + n * LDKB + k8 * 2) = vh;
        }
        __syncthreads();

        float acc[2][8][4];
#pragma unroll
        for (int mt = 0; mt < 2; mt++)
#pragma unroll
            for (int nt = 0; nt < 8; nt++)
#pragma unroll
                for (int q = 0; q < 4; q++) acc[mt][nt][q] = 0.f;

#pragma unroll 2
        for (int ks = 0; ks < 8; ks++) {
            const uint32_t kbb = ks * 32;
            uint32_t ah[2][4], al[2][4];
#pragma unroll
            for (int mt = 0; mt < 2; mt++) {
                uint32_t a = aoff0 + mt * 16 * LDKB + kbb;
                ldsm_x4(ah[mt], a);
                if (half == 0) ldsm_x4(al[mt], a + (AL - AH));
            }
#pragma unroll
            for (int ng = 0; ng < 4; ng++) {
                uint32_t bb[4];
                ldsm_x4(bb, boff0 + ng * 16 * LDKB + kbb);
#pragma unroll
                for (int mt = 0; mt < 2; mt++)
#pragma unroll
                    for (int s = 0; s < 2; s++) {
                        int nt = ng * 2 + s;
                        mma_f16(acc[mt][nt], ah[mt], bb[s * 2], bb[s * 2 + 1]);
                        if (half == 0)
                            mma_f16(acc[mt][nt], al[mt], bb[s * 2], bb[s * 2 + 1]);
                    }
            }
        }

#pragma unroll
        for (int mt = 0; mt < 2; mt++) {
#pragma unroll
            for (int nt = 0; nt < 8; nt++) {
                int jg = wn + nt * 8 + 2 * tig;
                int m0 = row0 + wm + mt * 16 + gid;
                int m1 = m0 + 8;
                if (half == 0) {
                    if (m0 < Nrows)
                        *reinterpret_cast<float2*>(p1 + (size_t)m0 * 128 + jg) =
                            make_float2(acc[mt][nt][0], acc[mt][nt][1]);
                    if (m1 < Nrows)
                        *reinterpret_cast<float2*>(p1 + (size_t)m1 * 128 + jg) =
                            make_float2(acc[mt][nt][2], acc[mt][nt][3]);
                } else {
                    if (m0 < Nrows)
                        *reinterpret_cast<uint32_t*>(t1 + (size_t)m0 * 128 + jg) =
                            pack_half2(acc[mt][nt][0], acc[mt][nt][1]);
                    if (m1 < Nrows)
                        *reinterpret_cast<uint32_t*>(t1 + (size_t)m1 * 128 + jg) =
                            pack_half2(acc[mt][nt][2], acc[mt][nt][3]);
                }
            }
        }
    }
}

// ---------------------------------------------------------------------------
// gemm2: C[128 x 128] = H(fp16 single plane) @ Bt2^T (fp16), ONE pass.
// SMEM = Ah + Bh = 69632 -> 2 CTAs/SM.
// ---------------------------------------------------------------------------
#define SMEM2 (2 * 128 * LDKB)

__global__ void __launch_bounds__(256, 2) gemm2_tc(
    const unsigned short* __restrict__ Ahh,
    const unsigned short* __restrict__ Bth,
    float* __restrict__ p2,
    unsigned short* __restrict__ t2,
    int Nrows) {
    extern __shared__ __align__(16) char smem[];
    constexpr int AH = 0;
    constexpr int BH = 128 * LDKB;

    const int tid = threadIdx.x;
    const int row0 = blockIdx.x * 128;

#pragma unroll
    for (int i = 0; i < 8; i++) {
        int l = tid + i * 256;
        int r = l >> 4;
        int k8 = (l & 15) * 8;
        uint4 vh = make_uint4(0, 0, 0, 0);
        int gr = row0 + r;
        if (gr < Nrows)
            vh = __ldg(reinterpret_cast<const uint4*>(Ahh + (size_t)gr * 128 + k8));
        *reinterpret_cast<uint4*>(smem + AH + r * LDKB + k8 * 2) = vh;
    }
#pragma unroll
    for (int i = 0; i < 8; i++) {
        int l = tid + i * 256;
        int n = l >> 4;
        int k8 = (l & 15) * 8;
        uint4 vh = __ldg(reinterpret_cast<const uint4*>(Bth + (size_t)n * 128 + k8));
        *reinterpret_cast<uint4*>(smem + BH + n * LDKB + k8 * 2) = vh;
    }
    __syncthreads();

    const int wid = tid >> 5;
    const int lane = tid & 31;
    const int lane8 = lane & 7;
    const int lt = lane >> 3;
    const int gid = lane >> 2;
    const int tig = lane & 3;
    const int wm = (wid & 3) * 32;
    const int wn = (wid >> 2) * 64;

    const uint32_t sb = smem_u32(smem);
    uint32_t aoff0 = sb + (uint32_t)((wm + (lt & 1) * 8 + lane8) * LDKB +
                                     (lt >> 1) * 16);
    uint32_t boff0 = sb + BH + (uint32_t)((wn + (lt >> 1) * 8 + lane8) * LDKB +
                                          (lt & 1) * 16);

    float acc[2][8][4];
#pragma unroll
    for (int mt = 0; mt < 2; mt++)
#pragma unroll
        for (int nt = 0; nt < 8; nt++)
#pragma unroll
            for (int q = 0; q < 4; q++) acc[mt][nt][q] = 0.f;

#pragma unroll 2
    for (int ks = 0; ks < 8; ks++) {
        const uint32_t kbb = ks * 32;
        uint32_t ah[2][4];
#pragma unroll
        for (int mt = 0; mt < 2; mt++)
            ldsm_x4(ah[mt], aoff0 + mt * 16 * LDKB + kbb);
#pragma unroll
        for (int ng = 0; ng < 4; ng++) {
            uint32_t bb[4];
            ldsm_x4(bb, boff0 + ng * 16 * LDKB + kbb);
#pragma unroll
            for (int mt = 0; mt < 2; mt++)
#pragma unroll
                for (int s = 0; s < 2; s++)
                    mma_f16(acc[mt][ng * 2 + s], ah[mt], bb[s * 2], bb[s * 2 + 1]);
        }
    }

#pragma unroll
    for (int mt = 0; mt < 2; mt++) {
#pragma unroll
        for (int nt = 0; nt < 8; nt++) {
            int jg = wn + nt * 8 + 2 * tig;
            int m0 = row0 + wm + mt * 16 + gid;
            int m1 = m0 + 8;
            if (jg < 64) {
                if (m0 < Nrows)
                    *reinterpret_cast<float2*>(p2 + (size_t)m0 * 64 + jg) =
                        make_float2(acc[mt][nt][0], acc[mt][nt][1]);
                if (m1 < Nrows)
                    *reinterpret_cast<float2*>(p2 + (size_t)m1 * 64 + jg) =
                        make_float2(acc[mt][nt][2], acc[mt][nt][3]);
            } else {
                int col = jg - 64;
                if (m0 < Nrows)
                    *reinterpret_cast<uint32_t*>(t2 + (size_t)m0 * 64 + col) =
                        pack_half2(acc[mt][nt][0], acc[mt][nt][1]);
                if (m1 < Nrows)
                    *reinterpret_cast<uint32_t*>(t2 + (size_t)m1 * 64 + col) =
                        pack_half2(acc[mt][nt][2], acc[mt][nt][3]);
            }
        }
    }
}

// ---------------------------------------------------------------------------
// gather_relu: h = relu(p1 + b1 + mean(t1[src])) -> fp16 single plane.
// Wide-load layout: 2 edges per warp step; half-warp per edge; lane loads
// uint4 (16B). Combine halves via shfl_xor(16); lanes 0-15 write 8 cols each.
// ---------------------------------------------------------------------------
__global__ void gather_relu_kernel(const unsigned short* __restrict__ t1,
                                   const float* __restrict__ p1,
                                   const float* __restrict__ bias,
                                   unsigned short* __restrict__ hh,
                                   int base, int limit) {
    int w = base + (int)(((size_t)blockIdx.x * blockDim.x + threadIdx.x) >> 5);
    int lane = threadIdx.x & 31;
    if (w >= limit) return;
    int beg = __ldg(&g_rowptr[w]);
    int end = __ldg(&g_rowptr[w + 1]);
    const int half = lane >> 4;
    const int li = lane & 15;
    const uint4* t4 = reinterpret_cast<const uint4*>(t1);  // row = 16 x uint4

    float acc[8];
#pragma unroll
    for (int i = 0; i < 8; i++) acc[i] = 0.f;

    int e = beg;
    for (; e + 8 <= end; e += 8) {
        int s[4];
#pragma unroll
        for (int q = 0; q < 4; q++) s[q] = __ldg(g_srcidx + e + q * 2 + half);
        uint4 v[4];
#pragma unroll
        for (int q = 0; q < 4; q++)
            v[q] = __ldg(t4 + (((size_t)s[q]) << 4) + li);
#pragma unroll
        for (int q = 0; q < 4; q++) acc8_add(acc, v[q]);
    }
    for (; e < end; e += 2) {
        int idx = e + half;
        if (idx < end) {
            int s = __ldg(g_srcidx + idx);
            uint4 v = __ldg(t4 + (((size_t)s) << 4) + li);
            acc8_add(acc, v);
        }
    }
#pragma unroll
    for (int i = 0; i < 8; i++)
        acc[i] += __shfl_xor_sync(0xffffffffu, acc[i], 16);

    if (lane < 16) {
        float inv = 1.0f / fmaxf((float)(end - beg), 1.0f);
        const float4* prow = reinterpret_cast<const float4*>(p1 + (size_t)w * 128 + li * 8);
        const float4* brow = reinterpret_cast<const float4*>(bias + li * 8);
        float4 pa = __ldg(prow), pb = __ldg(prow + 1);
        float4 ba = __ldg(brow), bb = __ldg(brow + 1);
        float r0 = fmaxf(fmaf(acc[0], inv, pa.x + ba.x), 0.f);
        float r1 = fmaxf(fmaf(acc[1], inv, pa.y + ba.y), 0.f);
        float r2 = fmaxf(fmaf(acc[2], inv, pa.z + ba.z), 0.f);
        float r3 = fmaxf(fmaf(acc[3], inv, pa.w + ba.w), 0.f);
        float r4 = fmaxf(fmaf(acc[4], inv, pb.x + bb.x), 0.f);
        float r5 = fmaxf(fmaf(acc[5], inv, pb.y + bb.y), 0.f);
        float r6 = fmaxf(fmaf(acc[6], inv, pb.z + bb.z), 0.f);
        float r7 = fmaxf(fmaf(acc[7], inv, pb.w + bb.w), 0.f);
        uint4 o;
        o.x = pack_half2(r0, r1); o.y = pack_half2(r2, r3);
        o.z = pack_half2(r4, r5); o.w = pack_half2(r6, r7);
        *reinterpret_cast<uint4*>(hh + (size_t)w * 128 + li * 8) = o;
    }
}

// ---------------------------------------------------------------------------
// gather_add: out = p2 + b2 + mean(t2[src]).
// 4 edges per warp step; 8 lanes per edge; lane loads uint4 (16B).
// Combine via shfl_xor(8)+shfl_xor(16); lanes 0-7 write 8 cols each.
// ---------------------------------------------------------------------------
__global__ void gather_add_kernel(const unsigned short* __restrict__ t2,
                                  const float* __restrict__ p2,
                                  const float* __restrict__ bias,
                                  float* __restrict__ out, int N) {
    int w = (int)(((size_t)blockIdx.x * blockDim.x + threadIdx.x) >> 5);
    int lane = threadIdx.x & 31;
    if (w >= N) return;
    int beg = __ldg(&g_rowptr[w]);
    int end = __ldg(&g_rowptr[w + 1]);
    const int grp = lane >> 3;
    const int li = lane & 7;
    const uint4* t4 = reinterpret_cast<const uint4*>(t2);  // row = 8 x uint4

    float acc[8];
#pragma unroll
    for (int i = 0; i < 8; i++) acc[i] = 0.f;

    int e = beg;
    for (; e + 8 <= end; e += 8) {
        int s0 = __ldg(g_srcidx + e + grp);
        int s1 = __ldg(g_srcidx + e + 4 + grp);
        uint4 v0 = __ldg(t4 + (((size_t)s0) << 3) + li);
        uint4 v1 = __ldg(t4 + (((size_t)s1) << 3) + li);
        acc8_add(acc, v0);
        acc8_add(acc, v1);
    }
    for (; e < end; e += 4) {
        int idx = e + grp;
        if (idx < end) {
            int s = __ldg(g_srcidx + idx);
            uint4 v = __ldg(t4 + (((size_t)s) << 3) + li);
            acc8_add(acc, v);
        }
    }
#pragma unroll
    for (int i = 0; i < 8; i++) {
        acc[i] += __shfl_xor_sync(0xffffffffu, acc[i], 8);
        acc[i] += __shfl_xor_sync(0xffffffffu, acc[i], 16);
    }

    if (lane < 8) {
        float inv = 1.0f / fmaxf((float)(end - beg), 1.0f);
        const float4* prow = reinterpret_cast<const float4*>(p2 + (size_t)w * 64 + li * 8);
        const float4* brow = reinterpret_cast<const float4*>(bias + li * 8);
        float4 pa = __ldg(prow), pb = __ldg(prow + 1);
        float4 ba = __ldg(brow), bb = __ldg(brow + 1);
        float4 oa, ob;
        oa.x = fmaf(acc[0], inv, pa.x + ba.x);
        oa.y = fmaf(acc[1], inv, pa.y + ba.y);
        oa.z = fmaf(acc[2], inv, pa.z + ba.z);
        oa.w = fmaf(acc[3], inv, pa.w + ba.w);
        ob.x = fmaf(acc[4], inv, pb.x + bb.x);
        ob.y = fmaf(acc[5], inv, pb.y + bb.y);
        ob.z = fmaf(acc[6], inv, pb.z + bb.z);
        ob.w = fmaf(acc[7], inv, pb.w + bb.w);
        float4* orow = reinterpret_cast<float4*>(out + (size_t)w * 64 + li * 8);
        orow[0] = oa;
        orow[1] = ob;
    }
}

// ---------------------------------------------------------------------------
// kernel_launch: CSR on side stream; merged gemm1 on main;
// gather_relu chunks (main) pipelined with gemm2 chunks (side).
// ---------------------------------------------------------------------------
extern "C" void kernel_launch(void* const* d_in, const int* in_sizes, int n_in,
                              void* d_out, int out_size) {
    const float* x   = (const float*)d_in[0];
    const int*   ei  = (const int*)d_in[1];
    const float* W1l = (const float*)d_in[2];
    const float* W1r = (const float*)d_in[3];
    const float* b1  = (const float*)d_in[4];
    const float* W2l = (const float*)d_in[5];
    const float* W2r = (const float*)d_in[6];
    const float* b2  = (const float*)d_in[7];
    float* out = (float*)d_out;

    const int N = in_sizes[0] / 128;
    const int E = in_sizes[1] / 2;
    const int* esrc = ei;
    const int* edst = ei + E;

    void *pp1, *pt1, *phh, *pp2, *pt2, *b1h, *b2h;
    cudaGetSymbolAddress(&pp1, g_p1);
    cudaGetSymbolAddress(&pt1, g_t1);
    cudaGetSymbolAddress(&phh, g_hh);
    cudaGetSymbolAddress(&pp2, g_p2);
    cudaGetSymbolAddress(&pt2, g_t2);
    cudaGetSymbolAddress(&b1h, g_bt1h);
    cudaGetSymbolAddress(&b2h, g_bt2h);
    float* p1 = (float*)pp1;
    unsigned short* t1 = (unsigned short*)pt1;
    unsigned short* hh = (unsigned short*)phh;
    float* p2 = (float*)pp2;
    unsigned short* t2 = (unsigned short*)pt2;
    const unsigned short* bt1h = (const unsigned short*)b1h;
    const unsigned short* bt2h = (const unsigned short*)b2h;

    static cudaStream_t side = nullptr;
    static cudaEvent_t ev_fork = nullptr, ev_join = nullptr, ev_g2 = nullptr;
    static cudaEvent_t ev_gr[4] = {nullptr, nullptr, nullptr, nullptr};
    static bool init_done = false;
    if (!init_done) {
        cudaStreamCreateWithFlags(&side, cudaStreamNonBlocking);
        cudaEventCreateWithFlags(&ev_fork, cudaEventDisableTiming);
        cudaEventCreateWithFlags(&ev_join, cudaEventDisableTiming);
        cudaEventCreateWithFlags(&ev_g2, cudaEventDisableTiming);
        for (int c = 0; c < 4; c++)
            cudaEventCreateWithFlags(&ev_gr[c], cudaEventDisableTiming);
        cudaFuncSetAttribute(gemm1_tc,
                             cudaFuncAttributeMaxDynamicSharedMemorySize, SMEM1);
        cudaFuncSetAttribute(gemm2_tc,
                             cudaFuncAttributeMaxDynamicSharedMemorySize, SMEM2);
        init_done = true;
    }

    const int gx = (N + 127) / 128;

    prep_weights<<<384, 128>>>(W1r, W1l, W2r, W2l);
    cudaEventRecord(ev_fork, 0);
    cudaStreamWaitEvent(side, ev_fork, 0);
    zero_count_kernel<<<(NODES + 255) / 256, 256, 0, side>>>();
    hist_kernel<<<(E + 255) / 256, 256, 0, side>>>(edst, E);
    gemm1_tc<<<gx, 256, SMEM1>>>(x, bt1h, p1, t1, N);
    scan_kernel<<<1, 1024, 0, side>>>(E);
    fill_kernel<<<(E + 255) / 256, 256, 0, side>>>(esrc, edst, E);
    cudaEventRecord(ev_join, side);

    cudaStreamWaitEvent(0, ev_join, 0);

    const int tpc = (gx + 3) / 4;
    for (int c = 0; c < 4; c++) {
        int t0 = c * tpc;
        if (t0 >= gx) { cudaEventRecord(ev_gr[c], 0); continue; }
        int tc = (gx - t0 < tpc) ? (gx - t0) : tpc;
        int r0 = t0 * 128;
        int rc = (N - r0 < tc * 128) ? (N - r0) : tc * 128;
        int wb = (rc * 32 + 255) / 256;
        gather_relu_kernel<<<wb, 256>>>(t1, p1, b1, hh, r0, r0 + rc);
        cudaEventRecord(ev_gr[c], 0);
        cudaStreamWaitEvent(side, ev_gr[c], 0);
        gemm2_tc<<<tc, 256, SMEM2, side>>>(
            hh + (size_t)r0 * 128, bt2h,
            p2 + (size_t)r0 * 64, t2 + (size_t)r0 * 64, rc);
    }
    cudaEventRecord(ev_g2, side);
    cudaStreamWaitEvent(0, ev_g2, 0);

    const int wblocks = (N * 32 + 255) / 256;
    gather_add_kernel<<<wblocks, 256>>>(t2, p2, b2, out, N);
}

// round 15
// speedup vs baseline: 1.0015x; 1.0015x over previous
#include <cuda_runtime.h>
#include <cuda_fp16.h>
#include <cstdint>
#include <cstddef>

#define NODES 100000
#define EDGES 1600000
#define NCH 8

// ---------------------------------------------------------------------------
// Scratch (__device__ globals; no allocation allowed anywhere).
// ---------------------------------------------------------------------------
__device__ float g_p1[(size_t)NODES * 128];            // layer1: x@W1_r (fp32)
__device__ unsigned short g_t1[(size_t)NODES * 128];   // layer1: x@W1_l (fp16)
__device__ unsigned short g_hh[(size_t)NODES * 128];   // h (fp16, single plane)
__device__ float g_p2[(size_t)NODES * 64];             // layer2: h@W2_r (fp32)
__device__ unsigned short g_t2[(size_t)NODES * 64];    // layer2: h@W2_l (fp16)
__device__ int   g_count[NODES];
__device__ int   g_rowptr[NODES + 1];
__device__ int   g_cursor[NODES];
__device__ int   g_srcidx[EDGES];
// Pre-transposed fp16 weights: Bt[n][k], n = output col.
__device__ unsigned short g_bt1h[256 * 128];
__device__ unsigned short g_bt2h[128 * 128];

// ---------------------------------------------------------------------------
// CSR build: zero counts -> histogram -> scan -> fill
// ---------------------------------------------------------------------------
__global__ void zero_count_kernel() {
    int i = blockIdx.x * blockDim.x + threadIdx.x;
    if (i < NODES) g_count[i] = 0;
}

__global__ void hist_kernel(const int* __restrict__ edst, int E) {
    int i = blockIdx.x * blockDim.x + threadIdx.x;
    if (i < E) atomicAdd(&g_count[__ldg(edst + i)], 1);
}

__global__ void scan_kernel(int E) {
    __shared__ int sums[1024];
    const int tid = threadIdx.x;
    const int CH = (NODES + 1023) / 1024;
    const int beg = tid * CH;
    const int end = min(beg + CH, NODES);
    int s = 0;
    for (int i = beg; i < end; i++) s += g_count[i];
    sums[tid] = s;
    __syncthreads();
    for (int off = 1; off < 1024; off <<= 1) {
        int v = (tid >= off) ? sums[tid - off] : 0;
        __syncthreads();
        sums[tid] += v;
        __syncthreads();
    }
    int run = (tid == 0) ? 0 : sums[tid - 1];
    for (int i = beg; i < end; i++) {
        g_rowptr[i] = run;
        g_cursor[i] = run;
        run += g_count[i];
    }
    if (tid == 0) g_rowptr[NODES] = E;
}

__global__ void fill_kernel(const int* __restrict__ esrc,
                            const int* __restrict__ edst, int E) {
    int i = blockIdx.x * blockDim.x + threadIdx.x;
    if (i >= E) return;
    int d = __ldg(edst + i);
    int s = __ldg(esrc + i);
    int pos = atomicAdd(&g_cursor[d], 1);
    g_srcidx[pos] = s;
}

// ---------------------------------------------------------------------------
// Weight prep: transpose to [n][k], fp16.
// ---------------------------------------------------------------------------
__global__ void prep_weights(const float* __restrict__ W1r,
                             const float* __restrict__ W1l,
                             const float* __restrict__ W2r,
                             const float* __restrict__ W2l) {
    int b = blockIdx.x;
    int k = threadIdx.x;
    float v;
    unsigned short* dh;
    if (b < 256) {
        int n = b;
        const float* W = (n < 128) ? W1r : W1l;
        v = __ldg(W + (size_t)k * 128 + (n & 127));
        dh = g_bt1h + n * 128 + k;
    } else {
        int n = b - 256;
        const float* W = (n < 64) ? W2r : W2l;
        v = __ldg(W + (size_t)k * 64 + (n & 63));
        dh = g_bt2h + n * 128 + k;
    }
    *dh = __half_as_ushort(__float2half_rn(v));
}

// ---------------------------------------------------------------------------
// GEMM helpers (mma.sync.m16n8k16.f16 + ldmatrix).
// ---------------------------------------------------------------------------
#define LDKB 272   // smem bytes per 128-col fp16 row (136 * 2)

__device__ __forceinline__ uint32_t smem_u32(const void* p) {
    uint32_t a;
    asm("{ .reg .u64 t; cvta.to.shared.u64 t, %1; cvt.u32.u64 %0, t; }"
        : "=r"(a) : "l"(p));
    return a;
}

__device__ __forceinline__ void ldsm_x4(uint32_t r[4], uint32_t addr) {
    asm volatile("ldmatrix.sync.aligned.m8n8.x4.shared.b16 {%0,%1,%2,%3}, [%4];"
                 : "=r"(r[0]), "=r"(r[1]), "=r"(r[2]), "=r"(r[3]) : "r"(addr));
}

__device__ __forceinline__ void mma_f16(float c[4], const uint32_t a[4],
                                        const uint32_t b0, const uint32_t b1) {
    asm volatile(
        "mma.sync.aligned.m16n8k16.row.col.f32.f16.f16.f32 "
        "{%0,%1,%2,%3}, {%4,%5,%6,%7}, {%8,%9}, {%0,%1,%2,%3};"
        : "+f"(c[0]), "+f"(c[1]), "+f"(c[2]), "+f"(c[3])
        : "r"(a[0]), "r"(a[1]), "r"(a[2]), "r"(a[3]), "r"(b0), "r"(b1));
}

__device__ __forceinline__ uint32_t pack_half2(float a, float b) {
    __half2 h = __floats2half2_rn(a, b);
    return *reinterpret_cast<uint32_t*>(&h);
}

// ---------------------------------------------------------------------------
// gemm1 (merged-loop): per CTA, A[128x128 fp32 -> fp16 h/l] loaded ONCE;
// loop over two 128-col B halves reusing the A smem.
//   half 0 (Bt rows   0..127): 2 passes (ah+al) -> p1 fp32
//   half 1 (Bt rows 128..255): 1 pass  (ah)     -> t1 fp16
// SMEM = Ah + Al + Bh = 104448 -> 2 CTAs/SM.
// ---------------------------------------------------------------------------
#define SMEM1 (3 * 128 * LDKB)

__global__ void __launch_bounds__(256, 2) gemm1_tc(
    const float* __restrict__ A,
    const unsigned short* __restrict__ Bth,
    float* __restrict__ p1,
    unsigned short* __restrict__ t1,
    int Nrows) {
    extern __shared__ __align__(16) char smem[];
    constexpr int AH = 0;
    constexpr int AL = 128 * LDKB;
    constexpr int BH = 2 * 128 * LDKB;

    const int tid = threadIdx.x;
    const int row0 = blockIdx.x * 128;

    // ---- A tile: load fp32, split to fp16 hi/lo (once) ----
#pragma unroll
    for (int i = 0; i < 16; i++) {
        int l = tid + i * 256;
        int r = l >> 5;
        int k4 = (l & 31) * 4;
        float4 v = make_float4(0.f, 0.f, 0.f, 0.f);
        int gr = row0 + r;
        if (gr < Nrows)
            v = __ldg(reinterpret_cast<const float4*>(A + (size_t)gr * 128 + k4));
        __half h0 = __float2half_rn(v.x), h1 = __float2half_rn(v.y);
        __half h2 = __float2half_rn(v.z), h3 = __float2half_rn(v.w);
        uint32_t ph0 = (uint32_t)__half_as_ushort(h0) |
                       ((uint32_t)__half_as_ushort(h1) << 16);
        uint32_t ph1 = (uint32_t)__half_as_ushort(h2) |
                       ((uint32_t)__half_as_ushort(h3) << 16);
        __half q0 = __float2half_rn(v.x - __half2float(h0));
        __half q1 = __float2half_rn(v.y - __half2float(h1));
        __half q2 = __float2half_rn(v.z - __half2float(h2));
        __half q3 = __float2half_rn(v.w - __half2float(h3));
        uint32_t pl0 = (uint32_t)__half_as_ushort(q0) |
                       ((uint32_t)__half_as_ushort(q1) << 16);
        uint32_t pl1 = (uint32_t)__half_as_ushort(q2) |
                       ((uint32_t)__half_as_ushort(q3) << 16);
        int off = r * LDKB + k4 * 2;
        *reinterpret_cast<uint2*>(smem + AH + off) = make_uint2(ph0, ph1);
        *reinterpret_cast<uint2*>(smem + AL + off) = make_uint2(pl0, pl1);
    }

    const int wid = tid >> 5;
    const int lane = tid & 31;
    const int lane8 = lane & 7;
    const int lt = lane >> 3;
    const int gid = lane >> 2;
    const int tig = lane & 3;
    const int wm = (wid & 3) * 32;
    const int wn = (wid >> 2) * 64;

    const uint32_t sb = smem_u32(smem);
    const uint32_t aoff0 = sb + (uint32_t)((wm + (lt & 1) * 8 + lane8) * LDKB +
                                           (lt >> 1) * 16);
    const uint32_t boff0 = sb + BH +
                           (uint32_t)((wn + (lt >> 1) * 8 + lane8) * LDKB +
                                      (lt & 1) * 16);

#pragma unroll
    for (int half = 0; half < 2; half++) {
        if (half) __syncthreads();
#pragma unroll
        for (int i = 0; i < 8; i++) {
            int l = tid + i * 256;
            int n = l >> 4;
            int k8 = (l & 15) * 8;
            uint4 vh = __ldg(reinterpret_cast<const uint4*>(
                Bth + ((size_t)(half * 128 + n)) * 128 + k8));
            *reinterpret_cast<uint4*>(smem + BH + n * LDKB + k8 * 2) = vh;
        }
        __syncthreads();

        float acc[2][8][4];
#pragma unroll
        for (int mt = 0; mt < 2; mt++)
#pragma unroll
            for (int nt = 0; nt < 8; nt++)
#pragma unroll
                for (int q = 0; q < 4; q++) acc[mt][nt][q] = 0.f;

#pragma unroll 2
        for (int ks = 0; ks < 8; ks++) {
            const uint32_t kbb = ks * 32;
            uint32_t ah[2][4], al[2][4];
#pragma unroll
            for (int mt = 0; mt < 2; mt++) {
                uint32_t a = aoff0 + mt * 16 * LDKB + kbb;
                ldsm_x4(ah[mt], a);
                if (half == 0) ldsm_x4(al[mt], a + (AL - AH));
            }
#pragma unroll
            for (int ng = 0; ng < 4; ng++) {
                uint32_t bb[4];
                ldsm_x4(bb, boff0 + ng * 16 * LDKB + kbb);
#pragma unroll
                for (int mt = 0; mt < 2; mt++)
#pragma unroll
                    for (int s = 0; s < 2; s++) {
                        int nt = ng * 2 + s;
                        mma_f16(acc[mt][nt], ah[mt], bb[s * 2], bb[s * 2 + 1]);
                        if (half == 0)
                            mma_f16(acc[mt][nt], al[mt], bb[s * 2], bb[s * 2 + 1]);
                    }
            }
        }

#pragma unroll
        for (int mt = 0; mt < 2; mt++) {
#pragma unroll
            for (int nt = 0; nt < 8; nt++) {
                int jg = wn + nt * 8 + 2 * tig;
                int m0 = row0 + wm + mt * 16 + gid;
                int m1 = m0 + 8;
                if (half == 0) {
                    if (m0 < Nrows)
                        *reinterpret_cast<float2*>(p1 + (size_t)m0 * 128 + jg) =
                            make_float2(acc[mt][nt][0], acc[mt][nt][1]);
                    if (m1 < Nrows)
                        *reinterpret_cast<float2*>(p1 + (size_t)m1 * 128 + jg) =
                            make_float2(acc[mt][nt][2], acc[mt][nt][3]);
                } else {
                    if (m0 < Nrows)
                        *reinterpret_cast<uint32_t*>(t1 + (size_t)m0 * 128 + jg) =
                            pack_half2(acc[mt][nt][0], acc[mt][nt][1]);
                    if (m1 < Nrows)
                        *reinterpret_cast<uint32_t*>(t1 + (size_t)m1 * 128 + jg) =
                            pack_half2(acc[mt][nt][2], acc[mt][nt][3]);
                }
            }
        }
    }
}

// ---------------------------------------------------------------------------
// gemm2: C[128 x 128] = H(fp16 single plane) @ Bt2^T (fp16), ONE pass.
// SMEM = Ah + Bh = 69632 -> 2 CTAs/SM.
// ---------------------------------------------------------------------------
#define SMEM2 (2 * 128 * LDKB)

__global__ void __launch_bounds__(256, 2) gemm2_tc(
    const unsigned short* __restrict__ Ahh,
    const unsigned short* __restrict__ Bth,
    float* __restrict__ p2,
    unsigned short* __restrict__ t2,
    int Nrows) {
    extern __shared__ __align__(16) char smem[];
    constexpr int AH = 0;
    constexpr int BH = 128 * LDKB;

    const int tid = threadIdx.x;
    const int row0 = blockIdx.x * 128;

#pragma unroll
    for (int i = 0; i < 8; i++) {
        int l = tid + i * 256;
        int r = l >> 4;
        int k8 = (l & 15) * 8;
        uint4 vh = make_uint4(0, 0, 0, 0);
        int gr = row0 + r;
        if (gr < Nrows)
            vh = __ldg(reinterpret_cast<const uint4*>(Ahh + (size_t)gr * 128 + k8));
        *reinterpret_cast<uint4*>(smem + AH + r * LDKB + k8 * 2) = vh;
    }
#pragma unroll
    for (int i = 0; i < 8; i++) {
        int l = tid + i * 256;
        int n = l >> 4;
        int k8 = (l & 15) * 8;
        uint4 vh = __ldg(reinterpret_cast<const uint4*>(Bth + (size_t)n * 128 + k8));
        *reinterpret_cast<uint4*>(smem + BH + n * LDKB + k8 * 2) = vh;
    }
    __syncthreads();

    const int wid = tid >> 5;
    const int lane = tid & 31;
    const int lane8 = lane & 7;
    const int lt = lane >> 3;
    const int gid = lane >> 2;
    const int tig = lane & 3;
    const int wm = (wid & 3) * 32;
    const int wn = (wid >> 2) * 64;

    const uint32_t sb = smem_u32(smem);
    uint32_t aoff0 = sb + (uint32_t)((wm + (lt & 1) * 8 + lane8) * LDKB +
                                     (lt >> 1) * 16);
    uint32_t boff0 = sb + BH + (uint32_t)((wn + (lt >> 1) * 8 + lane8) * LDKB +
                                          (lt & 1) * 16);

    float acc[2][8][4];
#pragma unroll
    for (int mt = 0; mt < 2; mt++)
#pragma unroll
        for (int nt = 0; nt < 8; nt++)
#pragma unroll
            for (int q = 0; q < 4; q++) acc[mt][nt][q] = 0.f;

#pragma unroll 2
    for (int ks = 0; ks < 8; ks++) {
        const uint32_t kbb = ks * 32;
        uint32_t ah[2][4];
#pragma unroll
        for (int mt = 0; mt < 2; mt++)
            ldsm_x4(ah[mt], aoff0 + mt * 16 * LDKB + kbb);
#pragma unroll
        for (int ng = 0; ng < 4; ng++) {
            uint32_t bb[4];
            ldsm_x4(bb, boff0 + ng * 16 * LDKB + kbb);
#pragma unroll
            for (int mt = 0; mt < 2; mt++)
#pragma unroll
                for (int s = 0; s < 2; s++)
                    mma_f16(acc[mt][ng * 2 + s], ah[mt], bb[s * 2], bb[s * 2 + 1]);
        }
    }

#pragma unroll
    for (int mt = 0; mt < 2; mt++) {
#pragma unroll
        for (int nt = 0; nt < 8; nt++) {
            int jg = wn + nt * 8 + 2 * tig;
            int m0 = row0 + wm + mt * 16 + gid;
            int m1 = m0 + 8;
            if (jg < 64) {
                if (m0 < Nrows)
                    *reinterpret_cast<float2*>(p2 + (size_t)m0 * 64 + jg) =
                        make_float2(acc[mt][nt][0], acc[mt][nt][1]);
                if (m1 < Nrows)
                    *reinterpret_cast<float2*>(p2 + (size_t)m1 * 64 + jg) =
                        make_float2(acc[mt][nt][2], acc[mt][nt][3]);
            } else {
                int col = jg - 64;
                if (m0 < Nrows)
                    *reinterpret_cast<uint32_t*>(t2 + (size_t)m0 * 64 + col) =
                        pack_half2(acc[mt][nt][0], acc[mt][nt][1]);
                if (m1 < Nrows)
                    *reinterpret_cast<uint32_t*>(t2 + (size_t)m1 * 64 + col) =
                        pack_half2(acc[mt][nt][2], acc[mt][nt][3]);
            }
        }
    }
}

// ---------------------------------------------------------------------------
// gather_relu (R13 form): h = relu(p1 + b1 + mean(t1[src])) -> fp16 plane.
// One warp per node, 8-edge unroll, uint2 (8B) per lane.
// ---------------------------------------------------------------------------
__global__ void gather_relu_kernel(const unsigned short* __restrict__ t1,
                                   const float* __restrict__ p1,
                                   const float* __restrict__ bias,
                                   unsigned short* __restrict__ hh,
                                   int base, int limit) {
    int w = base + (int)(((size_t)blockIdx.x * blockDim.x + threadIdx.x) >> 5);
    int lane = threadIdx.x & 31;
    if (w >= limit) return;
    int beg = __ldg(&g_rowptr[w]);
    int end = __ldg(&g_rowptr[w + 1]);
    float4 acc = make_float4(0.f, 0.f, 0.f, 0.f);
    const uint2* th = reinterpret_cast<const uint2*>(t1);
    int e = beg;
    for (; e + 8 <= end; e += 8) {
        int s[8];
#pragma unroll
        for (int q = 0; q < 8; q++) s[q] = __ldg(g_srcidx + e + q);
        uint2 v[8];
#pragma unroll
        for (int q = 0; q < 8; q++) v[q] = __ldg(th + (((size_t)s[q]) << 5) + lane);
#pragma unroll
        for (int q = 0; q < 8; q++) {
            float2 f0 = __half22float2(*reinterpret_cast<__half2*>(&v[q].x));
            float2 f1 = __half22float2(*reinterpret_cast<__half2*>(&v[q].y));
            acc.x += f0.x; acc.y += f0.y; acc.z += f1.x; acc.w += f1.y;
        }
    }
    for (; e < end; e++) {
        int s = __ldg(g_srcidx + e);
        uint2 v = __ldg(th + (((size_t)s) << 5) + lane);
        float2 f0 = __half22float2(*reinterpret_cast<__half2*>(&v.x));
        float2 f1 = __half22float2(*reinterpret_cast<__half2*>(&v.y));
        acc.x += f0.x; acc.y += f0.y; acc.z += f1.x; acc.w += f1.y;
    }
    float inv = 1.0f / fmaxf((float)(end - beg), 1.0f);
    float4 p = __ldg(reinterpret_cast<const float4*>(p1) + (((size_t)w) << 5) + lane);
    float4 b = __ldg(reinterpret_cast<const float4*>(bias) + lane);
    float rx = fmaxf(fmaf(acc.x, inv, p.x + b.x), 0.f);
    float ry = fmaxf(fmaf(acc.y, inv, p.y + b.y), 0.f);
    float rz = fmaxf(fmaf(acc.z, inv, p.z + b.z), 0.f);
    float rw = fmaxf(fmaf(acc.w, inv, p.w + b.w), 0.f);
    uint2 o = make_uint2(pack_half2(rx, ry), pack_half2(rz, rw));
    *reinterpret_cast<uint2*>(hh + (size_t)w * 128 + lane * 4) = o;
}

// ---------------------------------------------------------------------------
// gather_add (R13 form): out = p2 + b2 + mean(t2[src]); uint32 (4B) per lane.
// ---------------------------------------------------------------------------
__global__ void gather_add_kernel(const unsigned short* __restrict__ t2,
                                  const float* __restrict__ p2,
                                  const float* __restrict__ bias,
                                  float* __restrict__ out, int N) {
    int w = (int)(((size_t)blockIdx.x * blockDim.x + threadIdx.x) >> 5);
    int lane = threadIdx.x & 31;
    if (w >= N) return;
    int beg = __ldg(&g_rowptr[w]);
    int end = __ldg(&g_rowptr[w + 1]);
    float2 acc = make_float2(0.f, 0.f);
    const uint32_t* th = reinterpret_cast<const uint32_t*>(t2);
    int e = beg;
    for (; e + 8 <= end; e += 8) {
        int s[8];
#pragma unroll
        for (int q = 0; q < 8; q++) s[q] = __ldg(g_srcidx + e + q);
        uint32_t v[8];
#pragma unroll
        for (int q = 0; q < 8; q++) v[q] = __ldg(th + (((size_t)s[q]) << 5) + lane);
#pragma unroll
        for (int q = 0; q < 8; q++) {
            float2 f = __half22float2(*reinterpret_cast<__half2*>(&v[q]));
            acc.x += f.x; acc.y += f.y;
        }
    }
    for (; e < end; e++) {
        int s = __ldg(g_srcidx + e);
        uint32_t v = __ldg(th + (((size_t)s) << 5) + lane);
        float2 f = __half22float2(*reinterpret_cast<__half2*>(&v));
        acc.x += f.x; acc.y += f.y;
    }
    float inv = 1.0f / fmaxf((float)(end - beg), 1.0f);
    float2 p = __ldg(reinterpret_cast<const float2*>(p2) + (((size_t)w) << 5) + lane);
    float2 b = __ldg(reinterpret_cast<const float2*>(bias) + lane);
    float2 r;
    r.x = fmaf(acc.x, inv, p.x + b.x);
    r.y = fmaf(acc.y, inv, p.y + b.y);
    reinterpret_cast<float2*>(out)[(((size_t)w) << 5) + lane] = r;
}

// ---------------------------------------------------------------------------
// kernel_launch: CSR on side stream; merged gemm1 on main;
// gather_relu chunks (main) pipelined with gemm2 chunks (side), NCH chunks.
// ---------------------------------------------------------------------------
extern "C" void kernel_launch(void* const* d_in, const int* in_sizes, int n_in,
                              void* d_out, int out_size) {
    const float* x   = (const float*)d_in[0];
    const int*   ei  = (const int*)d_in[1];
    const float* W1l = (const float*)d_in[2];
    const float* W1r = (const float*)d_in[3];
    const float* b1  = (const float*)d_in[4];
    const float* W2l = (const float*)d_in[5];
    const float* W2r = (const float*)d_in[6];
    const float* b2  = (const float*)d_in[7];
    float* out = (float*)d_out;

    const int N = in_sizes[0] / 128;
    const int E = in_sizes[1] / 2;
    const int* esrc = ei;
    const int* edst = ei + E;

    void *pp1, *pt1, *phh, *pp2, *pt2, *b1h, *b2h;
    cudaGetSymbolAddress(&pp1, g_p1);
    cudaGetSymbolAddress(&pt1, g_t1);
    cudaGetSymbolAddress(&phh, g_hh);
    cudaGetSymbolAddress(&pp2, g_p2);
    cudaGetSymbolAddress(&pt2, g_t2);
    cudaGetSymbolAddress(&b1h, g_bt1h);
    cudaGetSymbolAddress(&b2h, g_bt2h);
    float* p1 = (float*)pp1;
    unsigned short* t1 = (unsigned short*)pt1;
    unsigned short* hh = (unsigned short*)phh;
    float* p2 = (float*)pp2;
    unsigned short* t2 = (unsigned short*)pt2;
    const unsigned short* bt1h = (const unsigned short*)b1h;
    const unsigned short* bt2h = (const unsigned short*)b2h;

    static cudaStream_t side = nullptr;
    static cudaEvent_t ev_fork = nullptr, ev_join = nullptr, ev_g2 = nullptr;
    static cudaEvent_t ev_gr[NCH];
    static bool init_done = false;
    if (!init_done) {
        cudaStreamCreateWithFlags(&side, cudaStreamNonBlocking);
        cudaEventCreateWithFlags(&ev_fork, cudaEventDisableTiming);
        cudaEventCreateWithFlags(&ev_join, cudaEventDisableTiming);
        cudaEventCreateWithFlags(&ev_g2, cudaEventDisableTiming);
        for (int c = 0; c < NCH; c++)
            cudaEventCreateWithFlags(&ev_gr[c], cudaEventDisableTiming);
        cudaFuncSetAttribute(gemm1_tc,
                             cudaFuncAttributeMaxDynamicSharedMemorySize, SMEM1);
        cudaFuncSetAttribute(gemm2_tc,
                             cudaFuncAttributeMaxDynamicSharedMemorySize, SMEM2);
        init_done = true;
    }

    const int gx = (N + 127) / 128;

    prep_weights<<<384, 128>>>(W1r, W1l, W2r, W2l);
    cudaEventRecord(ev_fork, 0);
    cudaStreamWaitEvent(side, ev_fork, 0);
    zero_count_kernel<<<(NODES + 255) / 256, 256, 0, side>>>();
    hist_kernel<<<(E + 255) / 256, 256, 0, side>>>(edst, E);
    gemm1_tc<<<gx, 256, SMEM1>>>(x, bt1h, p1, t1, N);
    scan_kernel<<<1, 1024, 0, side>>>(E);
    fill_kernel<<<(E + 255) / 256, 256, 0, side>>>(esrc, edst, E);
    cudaEventRecord(ev_join, side);

    cudaStreamWaitEvent(0, ev_join, 0);

    const int tpc = (gx + NCH - 1) / NCH;
    for (int c = 0; c < NCH; c++) {
        int t0 = c * tpc;
        if (t0 >= gx) { cudaEventRecord(ev_gr[c], 0); continue; }
        int tc = (gx - t0 < tpc) ? (gx - t0) : tpc;
        int r0 = t0 * 128;
        int rc = (N - r0 < tc * 128) ? (N - r0) : tc * 128;
        int wb = (rc * 32 + 255) / 256;
        gather_relu_kernel<<<wb, 256>>>(t1, p1, b1, hh, r0, r0 + rc);
        cudaEventRecord(ev_gr[c], 0);
        cudaStreamWaitEvent(side, ev_gr[c], 0);
        gemm2_tc<<<tc, 256, SMEM2, side>>>(
            hh + (size_t)r0 * 128, bt2h,
            p2 + (size_t)r0 * 64, t2 + (size_t)r0 * 64, rc);
    }
    cudaEventRecord(ev_g2, side);
    cudaStreamWaitEvent(0, ev_g2, 0);

    const int wblocks = (N * 32 + 255) / 256;
    gather_add_kernel<<<wblocks, 256>>>(t2, p2, b2, out, N);
}

// round 16
// speedup vs baseline: 1.0623x; 1.0607x over previous
#include <cuda_runtime.h>
#include <cuda_fp16.h>
#include <cstdint>
#include <cstddef>

#define NODES 100000
#define EDGES 1600000
#define NCH 4

// ---------------------------------------------------------------------------
// Scratch (__device__ globals; no allocation allowed anywhere).
// ---------------------------------------------------------------------------
__device__ unsigned short g_p1[(size_t)NODES * 128];   // layer1: x@W1_r (fp16)
__device__ unsigned short g_t1[(size_t)NODES * 128];   // layer1: x@W1_l (fp16)
__device__ unsigned short g_hh[(size_t)NODES * 128];   // h (fp16, single plane)
__device__ float g_p2[(size_t)NODES * 64];             // layer2: h@W2_r (fp32)
__device__ unsigned short g_t2[(size_t)NODES * 64];    // layer2: h@W2_l (fp16)
__device__ int   g_count[NODES];
__device__ int   g_rowptr[NODES + 1];
__device__ int   g_cursor[NODES];
__device__ int   g_srcidx[EDGES];
// Pre-transposed fp16 weights: Bt[n][k], n = output col.
__device__ unsigned short g_bt1h[256 * 128];
__device__ unsigned short g_bt2h[128 * 128];

// ---------------------------------------------------------------------------
// CSR build: zero counts -> histogram -> scan -> fill
// ---------------------------------------------------------------------------
__global__ void zero_count_kernel() {
    int i = blockIdx.x * blockDim.x + threadIdx.x;
    if (i < NODES) g_count[i] = 0;
}

__global__ void hist_kernel(const int* __restrict__ edst, int E) {
    int i = blockIdx.x * blockDim.x + threadIdx.x;
    if (i < E) atomicAdd(&g_count[__ldg(edst + i)], 1);
}

__global__ void scan_kernel(int E) {
    __shared__ int sums[1024];
    const int tid = threadIdx.x;
    const int CH = (NODES + 1023) / 1024;
    const int beg = tid * CH;
    const int end = min(beg + CH, NODES);
    int s = 0;
    for (int i = beg; i < end; i++) s += g_count[i];
    sums[tid] = s;
    __syncthreads();
    for (int off = 1; off < 1024; off <<= 1) {
        int v = (tid >= off) ? sums[tid - off] : 0;
        __syncthreads();
        sums[tid] += v;
        __syncthreads();
    }
    int run = (tid == 0) ? 0 : sums[tid - 1];
    for (int i = beg; i < end; i++) {
        g_rowptr[i] = run;
        g_cursor[i] = run;
        run += g_count[i];
    }
    if (tid == 0) g_rowptr[NODES] = E;
}

__global__ void fill_kernel(const int* __restrict__ esrc,
                            const int* __restrict__ edst, int E) {
    int i = blockIdx.x * blockDim.x + threadIdx.x;
    if (i >= E) return;
    int d = __ldg(edst + i);
    int s = __ldg(esrc + i);
    int pos = atomicAdd(&g_cursor[d], 1);
    g_srcidx[pos] = s;
}

// ---------------------------------------------------------------------------
// Weight prep: transpose to [n][k], fp16.
// ---------------------------------------------------------------------------
__global__ void prep_weights(const float* __restrict__ W1r,
                             const float* __restrict__ W1l,
                             const float* __restrict__ W2r,
                             const float* __restrict__ W2l) {
    int b = blockIdx.x;
    int k = threadIdx.x;
    float v;
    unsigned short* dh;
    if (b < 256) {
        int n = b;
        const float* W = (n < 128) ? W1r : W1l;
        v = __ldg(W + (size_t)k * 128 + (n & 127));
        dh = g_bt1h + n * 128 + k;
    } else {
        int n = b - 256;
        const float* W = (n < 64) ? W2r : W2l;
        v = __ldg(W + (size_t)k * 64 + (n & 63));
        dh = g_bt2h + n * 128 + k;
    }
    *dh = __half_as_ushort(__float2half_rn(v));
}

// ---------------------------------------------------------------------------
// GEMM helpers (mma.sync.m16n8k16.f16 + ldmatrix).
// ---------------------------------------------------------------------------
#define LDKB 272   // smem bytes per 128-col fp16 row (136 * 2)

__device__ __forceinline__ uint32_t smem_u32(const void* p) {
    uint32_t a;
    asm("{ .reg .u64 t; cvta.to.shared.u64 t, %1; cvt.u32.u64 %0, t; }"
        : "=r"(a) : "l"(p));
    return a;
}

__device__ __forceinline__ void ldsm_x4(uint32_t r[4], uint32_t addr) {
    asm volatile("ldmatrix.sync.aligned.m8n8.x4.shared.b16 {%0,%1,%2,%3}, [%4];"
                 : "=r"(r[0]), "=r"(r[1]), "=r"(r[2]), "=r"(r[3]) : "r"(addr));
}

__device__ __forceinline__ void mma_f16(float c[4], const uint32_t a[4],
                                        const uint32_t b0, const uint32_t b1) {
    asm volatile(
        "mma.sync.aligned.m16n8k16.row.col.f32.f16.f16.f32 "
        "{%0,%1,%2,%3}, {%4,%5,%6,%7}, {%8,%9}, {%0,%1,%2,%3};"
        : "+f"(c[0]), "+f"(c[1]), "+f"(c[2]), "+f"(c[3])
        : "r"(a[0]), "r"(a[1]), "r"(a[2]), "r"(a[3]), "r"(b0), "r"(b1));
}

__device__ __forceinline__ uint32_t pack_half2(float a, float b) {
    __half2 h = __floats2half2_rn(a, b);
    return *reinterpret_cast<uint32_t*>(&h);
}

// ---------------------------------------------------------------------------
// gemm1 (merged-loop): per CTA, A[128x128 fp32 -> fp16 h/l] loaded ONCE;
// loop over two 128-col B halves reusing the A smem.
//   half 0 (Bt rows   0..127): 2 passes (ah+al) -> p1 fp16
//   half 1 (Bt rows 128..255): 1 pass  (ah)     -> t1 fp16
// SMEM = Ah + Al + Bh = 104448 -> 2 CTAs/SM.
// ---------------------------------------------------------------------------
#define SMEM1 (3 * 128 * LDKB)

__global__ void __launch_bounds__(256, 2) gemm1_tc(
    const float* __restrict__ A,
    const unsigned short* __restrict__ Bth,
    unsigned short* __restrict__ p1,
    unsigned short* __restrict__ t1,
    int Nrows) {
    extern __shared__ __align__(16) char smem[];
    constexpr int AH = 0;
    constexpr int AL = 128 * LDKB;
    constexpr int BH = 2 * 128 * LDKB;

    const int tid = threadIdx.x;
    const int row0 = blockIdx.x * 128;

    // ---- A tile: load fp32, split to fp16 hi/lo (once) ----
#pragma unroll
    for (int i = 0; i < 16; i++) {
        int l = tid + i * 256;
        int r = l >> 5;
        int k4 = (l & 31) * 4;
        float4 v = make_float4(0.f, 0.f, 0.f, 0.f);
        int gr = row0 + r;
        if (gr < Nrows)
            v = __ldg(reinterpret_cast<const float4*>(A + (size_t)gr * 128 + k4));
        __half h0 = __float2half_rn(v.x), h1 = __float2half_rn(v.y);
        __half h2 = __float2half_rn(v.z), h3 = __float2half_rn(v.w);
        uint32_t ph0 = (uint32_t)__half_as_ushort(h0) |
                       ((uint32_t)__half_as_ushort(h1) << 16);
        uint32_t ph1 = (uint32_t)__half_as_ushort(h2) |
                       ((uint32_t)__half_as_ushort(h3) << 16);
        __half q0 = __float2half_rn(v.x - __half2float(h0));
        __half q1 = __float2half_rn(v.y - __half2float(h1));
        __half q2 = __float2half_rn(v.z - __half2float(h2));
        __half q3 = __float2half_rn(v.w - __half2float(h3));
        uint32_t pl0 = (uint32_t)__half_as_ushort(q0) |
                       ((uint32_t)__half_as_ushort(q1) << 16);
        uint32_t pl1 = (uint32_t)__half_as_ushort(q2) |
                       ((uint32_t)__half_as_ushort(q3) << 16);
        int off = r * LDKB + k4 * 2;
        *reinterpret_cast<uint2*>(smem + AH + off) = make_uint2(ph0, ph1);
        *reinterpret_cast<uint2*>(smem + AL + off) = make_uint2(pl0, pl1);
    }

    const int wid = tid >> 5;
    const int lane = tid & 31;
    const int lane8 = lane & 7;
    const int lt = lane >> 3;
    const int gid = lane >> 2;
    const int tig = lane & 3;
    const int wm = (wid & 3) * 32;
    const int wn = (wid >> 2) * 64;

    const uint32_t sb = smem_u32(smem);
    const uint32_t aoff0 = sb + (uint32_t)((wm + (lt & 1) * 8 + lane8) * LDKB +
                                           (lt >> 1) * 16);
    const uint32_t boff0 = sb + BH +
                           (uint32_t)((wn + (lt >> 1) * 8 + lane8) * LDKB +
                                      (lt & 1) * 16);

#pragma unroll
    for (int half = 0; half < 2; half++) {
        if (half) __syncthreads();
#pragma unroll
        for (int i = 0; i < 8; i++) {
            int l = tid + i * 256;
            int n = l >> 4;
            int k8 = (l & 15) * 8;
            uint4 vh = __ldg(reinterpret_cast<const uint4*>(
                Bth + ((size_t)(half * 128 + n)) * 128 + k8));
            *reinterpret_cast<uint4*>(smem + BH + n * LDKB + k8 * 2) = vh;
        }
        __syncthreads();

        float acc[2][8][4];
#pragma unroll
        for (int mt = 0; mt < 2; mt++)
#pragma unroll
            for (int nt = 0; nt < 8; nt++)
#pragma unroll
                for (int q = 0; q < 4; q++) acc[mt][nt][q] = 0.f;

#pragma unroll 2
        for (int ks = 0; ks < 8; ks++) {
            const uint32_t kbb = ks * 32;
            uint32_t ah[2][4], al[2][4];
#pragma unroll
            for (int mt = 0; mt < 2; mt++) {
                uint32_t a = aoff0 + mt * 16 * LDKB + kbb;
                ldsm_x4(ah[mt], a);
                if (half == 0) ldsm_x4(al[mt], a + (AL - AH));
            }
#pragma unroll
            for (int ng = 0; ng < 4; ng++) {
                uint32_t bb[4];
                ldsm_x4(bb, boff0 + ng * 16 * LDKB + kbb);
#pragma unroll
                for (int mt = 0; mt < 2; mt++)
#pragma unroll
                    for (int s = 0; s < 2; s++) {
                        int nt = ng * 2 + s;
                        mma_f16(acc[mt][nt], ah[mt], bb[s * 2], bb[s * 2 + 1]);
                        if (half == 0)
                            mma_f16(acc[mt][nt], al[mt], bb[s * 2], bb[s * 2 + 1]);
                    }
            }
        }

        // ---- epilogue: both halves write fp16 (p1 half0, t1 half1) ----
        unsigned short* dst = half ? t1 : p1;
#pragma unroll
        for (int mt = 0; mt < 2; mt++) {
#pragma unroll
            for (int nt = 0; nt < 8; nt++) {
                int jg = wn + nt * 8 + 2 * tig;
                int m0 = row0 + wm + mt * 16 + gid;
                int m1 = m0 + 8;
                if (m0 < Nrows)
                    *reinterpret_cast<uint32_t*>(dst + (size_t)m0 * 128 + jg) =
                        pack_half2(acc[mt][nt][0], acc[mt][nt][1]);
                if (m1 < Nrows)
                    *reinterpret_cast<uint32_t*>(dst + (size_t)m1 * 128 + jg) =
                        pack_half2(acc[mt][nt][2], acc[mt][nt][3]);
            }
        }
    }
}

// ---------------------------------------------------------------------------
// gemm2: C[128 x 128] = H(fp16 single plane) @ Bt2^T (fp16), ONE pass.
// SMEM = Ah + Bh = 69632 -> 2 CTAs/SM.
// ---------------------------------------------------------------------------
#define SMEM2 (2 * 128 * LDKB)

__global__ void __launch_bounds__(256, 2) gemm2_tc(
    const unsigned short* __restrict__ Ahh,
    const unsigned short* __restrict__ Bth,
    float* __restrict__ p2,
    unsigned short* __restrict__ t2,
    int Nrows) {
    extern __shared__ __align__(16) char smem[];
    constexpr int AH = 0;
    constexpr int BH = 128 * LDKB;

    const int tid = threadIdx.x;
    const int row0 = blockIdx.x * 128;

#pragma unroll
    for (int i = 0; i < 8; i++) {
        int l = tid + i * 256;
        int r = l >> 4;
        int k8 = (l & 15) * 8;
        uint4 vh = make_uint4(0, 0, 0, 0);
        int gr = row0 + r;
        if (gr < Nrows)
            vh = __ldg(reinterpret_cast<const uint4*>(Ahh + (size_t)gr * 128 + k8));
        *reinterpret_cast<uint4*>(smem + AH + r * LDKB + k8 * 2) = vh;
    }
#pragma unroll
    for (int i = 0; i < 8; i++) {
        int l = tid + i * 256;
        int n = l >> 4;
        int k8 = (l & 15) * 8;
        uint4 vh = __ldg(reinterpret_cast<const uint4*>(Bth + (size_t)n * 128 + k8));
        *reinterpret_cast<uint4*>(smem + BH + n * LDKB + k8 * 2) = vh;
    }
    __syncthreads();

    const int wid = tid >> 5;
    const int lane = tid & 31;
    const int lane8 = lane & 7;
    const int lt = lane >> 3;
    const int gid = lane >> 2;
    const int tig = lane & 3;
    const int wm = (wid & 3) * 32;
    const int wn = (wid >> 2) * 64;

    const uint32_t sb = smem_u32(smem);
    uint32_t aoff0 = sb + (uint32_t)((wm + (lt & 1) * 8 + lane8) * LDKB +
                                     (lt >> 1) * 16);
    uint32_t boff0 = sb + BH + (uint32_t)((wn + (lt >> 1) * 8 + lane8) * LDKB +
                                          (lt & 1) * 16);

    float acc[2][8][4];
#pragma unroll
    for (int mt = 0; mt < 2; mt++)
#pragma unroll
        for (int nt = 0; nt < 8; nt++)
#pragma unroll
            for (int q = 0; q < 4; q++) acc[mt][nt][q] = 0.f;

#pragma unroll 2
    for (int ks = 0; ks < 8; ks++) {
        const uint32_t kbb = ks * 32;
        uint32_t ah[2][4];
#pragma unroll
        for (int mt = 0; mt < 2; mt++)
            ldsm_x4(ah[mt], aoff0 + mt * 16 * LDKB + kbb);
#pragma unroll
        for (int ng = 0; ng < 4; ng++) {
            uint32_t bb[4];
            ldsm_x4(bb, boff0 + ng * 16 * LDKB + kbb);
#pragma unroll
            for (int mt = 0; mt < 2; mt++)
#pragma unroll
                for (int s = 0; s < 2; s++)
                    mma_f16(acc[mt][ng * 2 + s], ah[mt], bb[s * 2], bb[s * 2 + 1]);
        }
    }

#pragma unroll
    for (int mt = 0; mt < 2; mt++) {
#pragma unroll
        for (int nt = 0; nt < 8; nt++) {
            int jg = wn + nt * 8 + 2 * tig;
            int m0 = row0 + wm + mt * 16 + gid;
            int m1 = m0 + 8;
            if (jg < 64) {
                if (m0 < Nrows)
                    *reinterpret_cast<float2*>(p2 + (size_t)m0 * 64 + jg) =
                        make_float2(acc[mt][nt][0], acc[mt][nt][1]);
                if (m1 < Nrows)
                    *reinterpret_cast<float2*>(p2 + (size_t)m1 * 64 + jg) =
                        make_float2(acc[mt][nt][2], acc[mt][nt][3]);
            } else {
                int col = jg - 64;
                if (m0 < Nrows)
                    *reinterpret_cast<uint32_t*>(t2 + (size_t)m0 * 64 + col) =
                        pack_half2(acc[mt][nt][0], acc[mt][nt][1]);
                if (m1 < Nrows)
                    *reinterpret_cast<uint32_t*>(t2 + (size_t)m1 * 64 + col) =
                        pack_half2(acc[mt][nt][2], acc[mt][nt][3]);
            }
        }
    }
}

// ---------------------------------------------------------------------------
// gather_relu: h = relu(p1 + b1 + mean(t1[src])) -> fp16 plane.
// One warp per node, 8-edge unroll, uint2 (8B) per lane. p1 now fp16.
// ---------------------------------------------------------------------------
__global__ void gather_relu_kernel(const unsigned short* __restrict__ t1,
                                   const unsigned short* __restrict__ p1,
                                   const float* __restrict__ bias,
                                   unsigned short* __restrict__ hh,
                                   int base, int limit) {
    int w = base + (int)(((size_t)blockIdx.x * blockDim.x + threadIdx.x) >> 5);
    int lane = threadIdx.x & 31;
    if (w >= limit) return;
    int beg = __ldg(&g_rowptr[w]);
    int end = __ldg(&g_rowptr[w + 1]);
    float4 acc = make_float4(0.f, 0.f, 0.f, 0.f);
    const uint2* th = reinterpret_cast<const uint2*>(t1);
    int e = beg;
    for (; e + 8 <= end; e += 8) {
        int s[8];
#pragma unroll
        for (int q = 0; q < 8; q++) s[q] = __ldg(g_srcidx + e + q);
        uint2 v[8];
#pragma unroll
        for (int q = 0; q < 8; q++) v[q] = __ldg(th + (((size_t)s[q]) << 5) + lane);
#pragma unroll
        for (int q = 0; q < 8; q++) {
            float2 f0 = __half22float2(*reinterpret_cast<__half2*>(&v[q].x));
            float2 f1 = __half22float2(*reinterpret_cast<__half2*>(&v[q].y));
            acc.x += f0.x; acc.y += f0.y; acc.z += f1.x; acc.w += f1.y;
        }
    }
    for (; e < end; e++) {
        int s = __ldg(g_srcidx + e);
        uint2 v = __ldg(th + (((size_t)s) << 5) + lane);
        float2 f0 = __half22float2(*reinterpret_cast<__half2*>(&v.x));
        float2 f1 = __half22float2(*reinterpret_cast<__half2*>(&v.y));
        acc.x += f0.x; acc.y += f0.y; acc.z += f1.x; acc.w += f1.y;
    }
    float inv = 1.0f / fmaxf((float)(end - beg), 1.0f);
    uint2 pv = __ldg(reinterpret_cast<const uint2*>(p1) + (((size_t)w) << 5) + lane);
    float2 p0 = __half22float2(*reinterpret_cast<__half2*>(&pv.x));
    float2 p1v = __half22float2(*reinterpret_cast<__half2*>(&pv.y));
    float4 b = __ldg(reinterpret_cast<const float4*>(bias) + lane);
    float rx = fmaxf(fmaf(acc.x, inv, p0.x + b.x), 0.f);
    float ry = fmaxf(fmaf(acc.y, inv, p0.y + b.y), 0.f);
    float rz = fmaxf(fmaf(acc.z, inv, p1v.x + b.z), 0.f);
    float rw = fmaxf(fmaf(acc.w, inv, p1v.y + b.w), 0.f);
    uint2 o = make_uint2(pack_half2(rx, ry), pack_half2(rz, rw));
    *reinterpret_cast<uint2*>(hh + (size_t)w * 128 + lane * 4) = o;
}

// ---------------------------------------------------------------------------
// gather_add: out = p2 + b2 + mean(t2[src]); uint32 (4B) per lane.
// ---------------------------------------------------------------------------
__global__ void gather_add_kernel(const unsigned short* __restrict__ t2,
                                  const float* __restrict__ p2,
                                  const float* __restrict__ bias,
                                  float* __restrict__ out, int N) {
    int w = (int)(((size_t)blockIdx.x * blockDim.x + threadIdx.x) >> 5);
    int lane = threadIdx.x & 31;
    if (w >= N) return;
    int beg = __ldg(&g_rowptr[w]);
    int end = __ldg(&g_rowptr[w + 1]);
    float2 acc = make_float2(0.f, 0.f);
    const uint32_t* th = reinterpret_cast<const uint32_t*>(t2);
    int e = beg;
    for (; e + 8 <= end; e += 8) {
        int s[8];
#pragma unroll
        for (int q = 0; q < 8; q++) s[q] = __ldg(g_srcidx + e + q);
        uint32_t v[8];
#pragma unroll
        for (int q = 0; q < 8; q++) v[q] = __ldg(th + (((size_t)s[q]) << 5) + lane);
#pragma unroll
        for (int q = 0; q < 8; q++) {
            float2 f = __half22float2(*reinterpret_cast<__half2*>(&v[q]));
            acc.x += f.x; acc.y += f.y;
        }
    }
    for (; e < end; e++) {
        int s = __ldg(g_srcidx + e);
        uint32_t v = __ldg(th + (((size_t)s) << 5) + lane);
        float2 f = __half22float2(*reinterpret_cast<__half2*>(&v));
        acc.x += f.x; acc.y += f.y;
    }
    float inv = 1.0f / fmaxf((float)(end - beg), 1.0f);
    float2 p = __ldg(reinterpret_cast<const float2*>(p2) + (((size_t)w) << 5) + lane);
    float2 b = __ldg(reinterpret_cast<const float2*>(bias) + lane);
    float2 r;
    r.x = fmaf(acc.x, inv, p.x + b.x);
    r.y = fmaf(acc.y, inv, p.y + b.y);
    reinterpret_cast<float2*>(out)[(((size_t)w) << 5) + lane] = r;
}

// ---------------------------------------------------------------------------
// kernel_launch: CSR on side stream; merged gemm1 on main;
// gather_relu chunks (main) pipelined with gemm2 chunks (side), NCH=4.
// ---------------------------------------------------------------------------
extern "C" void kernel_launch(void* const* d_in, const int* in_sizes, int n_in,
                              void* d_out, int out_size) {
    const float* x   = (const float*)d_in[0];
    const int*   ei  = (const int*)d_in[1];
    const float* W1l = (const float*)d_in[2];
    const float* W1r = (const float*)d_in[3];
    const float* b1  = (const float*)d_in[4];
    const float* W2l = (const float*)d_in[5];
    const float* W2r = (const float*)d_in[6];
    const float* b2  = (const float*)d_in[7];
    float* out = (float*)d_out;

    const int N = in_sizes[0] / 128;
    const int E = in_sizes[1] / 2;
    const int* esrc = ei;
    const int* edst = ei + E;

    void *pp1, *pt1, *phh, *pp2, *pt2, *b1h, *b2h;
    cudaGetSymbolAddress(&pp1, g_p1);
    cudaGetSymbolAddress(&pt1, g_t1);
    cudaGetSymbolAddress(&phh, g_hh);
    cudaGetSymbolAddress(&pp2, g_p2);
    cudaGetSymbolAddress(&pt2, g_t2);
    cudaGetSymbolAddress(&b1h, g_bt1h);
    cudaGetSymbolAddress(&b2h, g_bt2h);
    unsigned short* p1 = (unsigned short*)pp1;
    unsigned short* t1 = (unsigned short*)pt1;
    unsigned short* hh = (unsigned short*)phh;
    float* p2 = (float*)pp2;
    unsigned short* t2 = (unsigned short*)pt2;
    const unsigned short* bt1h = (const unsigned short*)b1h;
    const unsigned short* bt2h = (const unsigned short*)b2h;

    static cudaStream_t side = nullptr;
    static cudaEvent_t ev_fork = nullptr, ev_join = nullptr, ev_g2 = nullptr;
    static cudaEvent_t ev_gr[NCH];
    static bool init_done = false;
    if (!init_done) {
        cudaStreamCreateWithFlags(&side, cudaStreamNonBlocking);
        cudaEventCreateWithFlags(&ev_fork, cudaEventDisableTiming);
        cudaEventCreateWithFlags(&ev_join, cudaEventDisableTiming);
        cudaEventCreateWithFlags(&ev_g2, cudaEventDisableTiming);
        for (int c = 0; c < NCH; c++)
            cudaEventCreateWithFlags(&ev_gr[c], cudaEventDisableTiming);
        cudaFuncSetAttribute(gemm1_tc,
                             cudaFuncAttributeMaxDynamicSharedMemorySize, SMEM1);
        cudaFuncSetAttribute(gemm2_tc,
                             cudaFuncAttributeMaxDynamicSharedMemorySize, SMEM2);
        init_done = true;
    }

    const int gx = (N + 127) / 128;

    prep_weights<<<384, 128>>>(W1r, W1l, W2r, W2l);
    cudaEventRecord(ev_fork, 0);
    cudaStreamWaitEvent(side, ev_fork, 0);
    zero_count_kernel<<<(NODES + 255) / 256, 256, 0, side>>>();
    hist_kernel<<<(E + 255) / 256, 256, 0, side>>>(edst, E);
    gemm1_tc<<<gx, 256, SMEM1>>>(x, bt1h, p1, t1, N);
    scan_kernel<<<1, 1024, 0, side>>>(E);
    fill_kernel<<<(E + 255) / 256, 256, 0, side>>>(esrc, edst, E);
    cudaEventRecord(ev_join, side);

    cudaStreamWaitEvent(0, ev_join, 0);

    const int tpc = (gx + NCH - 1) / NCH;
    for (int c = 0; c < NCH; c++) {
        int t0 = c * tpc;
        if (t0 >= gx) { cudaEventRecord(ev_gr[c], 0); continue; }
        int tc = (gx - t0 < tpc) ? (gx - t0) : tpc;
        int r0 = t0 * 128;
        int rc = (N - r0 < tc * 128) ? (N - r0) : tc * 128;
        int wb = (rc * 32 + 255) / 256;
        gather_relu_kernel<<<wb, 256>>>(t1, p1, b1, hh, r0, r0 + rc);
        cudaEventRecord(ev_gr[c], 0);
        cudaStreamWaitEvent(side, ev_gr[c], 0);
        gemm2_tc<<<tc, 256, SMEM2, side>>>(
            hh + (size_t)r0 * 128, bt2h,
            p2 + (size_t)r0 * 64, t2 + (size_t)r0 * 64, rc);
    }
    cudaEventRecord(ev_g2, side);
    cudaStreamWaitEvent(0, ev_g2, 0);

    const int wblocks = (N * 32 + 255) / 256;
    gather_add_kernel<<<wblocks, 256>>>(t2, p2, b2, out, N);
}